// round 10
// baseline (speedup 1.0000x reference)
#include <cuda_runtime.h>
#include <cstdint>

// Reference collapses: softmax(const(-9e15)) == uniform 1/N  =>  adj/a/e dead.
//   out[i,:] = relu( (colsum(h) @ W) / N )  -- one 64-float row broadcast 8192x.
// One kernel, grid 256 x 1024. NO dependent global-load chains anywhere:
//   A: cp.async double-buffered partial column sums (register-free MLP)
//   B: per-block projection, 8 independent coalesced W loads/thread + smem tree
//   C: last-arrival reducer: 4 independent loads/thread over g_pproj + smem tree
//   D: single-flag spin, broadcast 2MB.

#define N_ROWSC 8192
#define F_INC   512
#define F_OUTC  64
#define GRID    256
#define THREADS 1024
#define TOTAL_F4 (N_ROWSC * F_INC / 4)        // 1,048,576
#define STRIDE   (GRID * THREADS)             // 262,144
#define OUT_F4   (N_ROWSC * F_OUTC / 4)       // 131,072

__device__ float4 g_pproj4[GRID * 16];            // 64 KB per-block projections
__device__ float4 g_row4[16];                     // final row
__device__ unsigned long long g_cnt;              // monotonic across replays
__device__ volatile unsigned long long g_flag;    // epoch of completed row

__device__ __forceinline__ uint32_t smem_u32(const void* p) {
    return (uint32_t)__cvta_generic_to_shared(p);
}
__device__ __forceinline__ void cp16(uint32_t dst, const void* src) {
    asm volatile("cp.async.cg.shared.global [%0], [%1], 16;" :: "r"(dst), "l"(src));
}
#define CP_COMMIT() asm volatile("cp.async.commit_group;")
#define CP_WAIT(n)  asm volatile("cp.async.wait_group %0;" :: "n"(n))

__device__ __forceinline__ void f4add(float4& a, const float4& v) {
    a.x += v.x; a.y += v.y; a.z += v.z; a.w += v.w;
}

__global__ __launch_bounds__(THREADS)
void gat_kernel(const float4* __restrict__ h4,
                const float4* __restrict__ W4,
                float4*       __restrict__ out)
{
    __shared__ float4 stage[2][THREADS];      // 32 KB (A staging; reused B/C)
    __shared__ float  sf[F_INC];              // 2 KB block colsum
    __shared__ float4 srow4[16];              // 256 B
    __shared__ unsigned long long s_ticket;

    const int t = threadIdx.x;
    const int b = blockIdx.x;

    // ---- A: column sums via cp.async, 2-deep pipeline ----
    {
        const float4* p = h4 + (b * THREADS + t);   // colgroup = t & 127 (strides %128==0)
        const uint32_t st0 = smem_u32(&stage[0][t]);
        const uint32_t st1 = smem_u32(&stage[1][t]);
        cp16(st0, p);              CP_COMMIT();     // g0
        cp16(st1, p + STRIDE);     CP_COMMIT();     // g1
        CP_WAIT(1);
        float4 acc = stage[0][t];
        cp16(st0, p + 2 * STRIDE); CP_COMMIT();     // g2
        CP_WAIT(1);
        f4add(acc, stage[1][t]);
        cp16(st1, p + 3 * STRIDE); CP_COMMIT();     // g3
        CP_WAIT(1);
        f4add(acc, stage[0][t]);
        CP_WAIT(0);
        f4add(acc, stage[1][t]);
        stage[0][t] = acc;                          // publish per-thread partial
    }
    __syncthreads();
    if (t < 128) {                            // fixed order -> deterministic
        float4 a = stage[0][t];
        #pragma unroll
        for (int j = 1; j < 8; ++j) f4add(a, stage[0][t + 128 * j]);  // same colgroup
        sf[t * 4 + 0] = a.x; sf[t * 4 + 1] = a.y;
        sf[t * 4 + 2] = a.z; sf[t * 4 + 3] = a.w;
    }
    __syncthreads();

    // ---- B: project colsum through W; 8 indep coalesced float4 loads ----
    {
        // i = t + j*1024 covers all 8192 float4 of W; colgroup = i&15 = t&15 (const),
        // k = i>>4 = (t>>4) + 64j.  po = sum over this thread's k subset.
        float4 po = make_float4(0.f, 0.f, 0.f, 0.f);
        #pragma unroll
        for (int j = 0; j < 8; ++j) {
            const int i = t + j * THREADS;
            const float4 w = W4[i];
            const float  s = sf[(t >> 4) + j * 64];
            po.x = fmaf(s, w.x, po.x); po.y = fmaf(s, w.y, po.y);
            po.z = fmaf(s, w.z, po.z); po.w = fmaf(s, w.w, po.w);
        }
        stage[0][t] = po;
    }
    __syncthreads();
    if (t < 256) {                            // tree: 1024 -> 256 (same t&15)
        float4 a = stage[0][t];
        f4add(a, stage[0][t + 256]); f4add(a, stage[0][t + 512]);
        f4add(a, stage[0][t + 768]);
        stage[1][t] = a;
    }
    __syncthreads();
    if (t < 16) {                             // 256 -> 16, fixed order
        float4 a = stage[1][t];
        #pragma unroll
        for (int m = 1; m < 16; ++m) f4add(a, stage[1][t + 16 * m]);
        g_pproj4[b * 16 + t] = a;
    }
    __threadfence();
    __syncthreads();

    if (t == 0) s_ticket = atomicAdd(&g_cnt, 1ULL);
    __syncthreads();
    const unsigned long long ticket = s_ticket;
    const unsigned long long launch = ticket / GRID;   // replay epoch

    if (ticket % GRID == GRID - 1) {
        __threadfence();                      // acquire: all g_pproj4 visible
        // ---- C: reduce 256x16 float4 (64 KB); 4 indep coalesced loads ----
        {
            float4 a = __ldcg(&g_pproj4[t]);              // idx&15 = t&15 for all
            float4 v1 = __ldcg(&g_pproj4[t + 1024]);
            float4 v2 = __ldcg(&g_pproj4[t + 2048]);
            float4 v3 = __ldcg(&g_pproj4[t + 3072]);
            f4add(a, v1); f4add(a, v2); f4add(a, v3);     // fixed order
            stage[0][t] = a;
        }
        __syncthreads();
        if (t < 256) {
            float4 a = stage[0][t];
            f4add(a, stage[0][t + 256]); f4add(a, stage[0][t + 512]);
            f4add(a, stage[0][t + 768]);
            stage[1][t] = a;
        }
        __syncthreads();
        if (t < 16) {                         // 256 -> 16, fixed order
            float4 a = stage[1][t];
            #pragma unroll
            for (int m = 1; m < 16; ++m) f4add(a, stage[1][t + 16 * m]);
            const float inv = 1.0f / (float)N_ROWSC;
            a.x = fmaxf(a.x * inv, 0.f); a.y = fmaxf(a.y * inv, 0.f);
            a.z = fmaxf(a.z * inv, 0.f); a.w = fmaxf(a.w * inv, 0.f);
            g_row4[t] = a;
        }
        __threadfence();
        __syncthreads();
        if (t == 0) g_flag = launch + 1;      // release
    } else {
        if (t == 0) {                         // single-word plain-load spin
            while (g_flag < launch + 1) __nanosleep(64);
            __threadfence();                  // acquire
        }
        __syncthreads();
    }

    // ---- D: broadcast; each block writes its 512-float4 slice ----
    if (t < 16) srow4[t] = __ldcg(&g_row4[t]);
    __syncthreads();
    if (t < OUT_F4 / GRID) {                  // 512 per block
        out[b * (OUT_F4 / GRID) + t] = srow4[t & 15];   // 512 %16==0 -> colgrp t&15
    }
}

extern "C" void kernel_launch(void* const* d_in, const int* in_sizes, int n_in,
                              void* d_out, int out_size) {
    (void)in_sizes; (void)n_in; (void)out_size;
    const float* h = (const float*)d_in[0];   // (8192, 512) fp32
    // d_in[1] = adj (8192,8192) -- dead code, never read
    const float* W = (const float*)d_in[2];   // (512, 64) fp32
    // d_in[3] = a (128,1)       -- dead code, never read
    float* out = (float*)d_out;               // (8192, 64) fp32

    gat_kernel<<<GRID, THREADS>>>((const float4*)h, (const float4*)W,
                                  (float4*)out);
}

// round 12
// speedup vs baseline: 1.1813x; 1.1813x over previous
#include <cuda_runtime.h>

// Reference collapses: softmax(const(-9e15)) == uniform 1/N  =>  adj/a/e dead.
//   out[i,:] = relu( (colsum(h) @ W) / N )  -- one 64-float row broadcast 8192x.
// One kernel, grid 128 x 1024 (R5 phase A + R8 per-block projection + trimmed tail):
//   A: partial column sums, 8 indep float4 loads/thread (exact cover)
//   B: per-block projection through W (8 indep coalesced W loads/thread + smem tree)
//      -> g_pproj4[b] (16 float4)  => reducer payload only 32 KB
//   C: ticket; last arrival sums 2048 float4 (2 indep loads/thread + tree), relu
//   D: 32-bit flag spin (light backoff); broadcast 2MB (1 float4 store/thread).

#define N_ROWSC 8192
#define F_INC   512
#define F_OUTC  64
#define GRID    128
#define THREADS 1024
#define TOTAL_F4 (N_ROWSC * F_INC / 4)        // 1,048,576
#define STRIDE   (GRID * THREADS)             // 131,072 (multiple of 128)
#define LOADS_PT (TOTAL_F4 / STRIDE)          // 8 (exact)
#define OUT_F4   (N_ROWSC * F_OUTC / 4)       // 131,072  (1024 per block)

__device__ float4 g_pproj4[GRID * 16];            // 32 KB per-block projections
__device__ float4 g_row4[16];                     // final row
__device__ unsigned long long g_cnt;              // monotonic across replays
__device__ volatile unsigned g_flag;              // epoch of completed row (32-bit)

__device__ __forceinline__ void f4add(float4& a, const float4& v) {
    a.x += v.x; a.y += v.y; a.z += v.z; a.w += v.w;
}

__global__ __launch_bounds__(THREADS)
void gat_kernel(const float4* __restrict__ h4,
                const float4* __restrict__ W4,
                float4*       __restrict__ out)
{
    __shared__ float4 s4[THREADS];            // 16 KB (reused across phases)
    __shared__ float4 s4b[256];               // 4 KB tree stage
    __shared__ float  sf[F_INC];              // 2 KB block colsum
    __shared__ float4 srow4[16];              // 256 B
    __shared__ unsigned long long s_ticket;

    const int t = threadIdx.x;
    const int b = blockIdx.x;

    // Warm W (8192 float4 = 131 KB) into L2; blocks 0..7 cover it exactly.
    if (b < 8) {
        float4 w = __ldcg(&W4[b * THREADS + t]);
        asm volatile("" :: "f"(w.x), "f"(w.y), "f"(w.z), "f"(w.w));
    }

    // ---- A: partial column sums; 8 independent float4 loads (R5-proven) ----
    {
        const int gid = b * THREADS + t;      // stride mult of 128 -> colgrp = t & 127
        float4 acc = make_float4(0.f, 0.f, 0.f, 0.f);
        #pragma unroll
        for (int k = 0; k < LOADS_PT; ++k) {
            float4 v = h4[gid + k * STRIDE];
            f4add(acc, v);                    // fixed order -> deterministic
        }
        s4[t] = acc;
    }
    __syncthreads();
    if (t < 128) {                            // 8 partials per column group, fixed order
        float4 a = s4[t];
        #pragma unroll
        for (int j = 1; j < 8; ++j) f4add(a, s4[t + 128 * j]);
        sf[t * 4 + 0] = a.x; sf[t * 4 + 1] = a.y;
        sf[t * 4 + 2] = a.z; sf[t * 4 + 3] = a.w;
    }
    __syncthreads();

    // ---- B: project colsum through W; 8 indep coalesced W float4 loads ----
    {
        // i = t + j*1024 covers all 8192 float4 of W exactly once.
        // colgroup(i) = i & 15 = t & 15 (constant per thread); k(i) = i >> 4.
        float4 po = make_float4(0.f, 0.f, 0.f, 0.f);
        #pragma unroll
        for (int j = 0; j < 8; ++j) {
            const float4 w = W4[t + j * THREADS];         // L2-warm
            const float  s = sf[(t >> 4) + j * 64];
            po.x = fmaf(s, w.x, po.x); po.y = fmaf(s, w.y, po.y);
            po.z = fmaf(s, w.z, po.z); po.w = fmaf(s, w.w, po.w);
        }
        s4[t] = po;
    }
    __syncthreads();
    if (t < 256) {                            // 1024 -> 256, same colgroup (t&15)
        float4 a = s4[t];
        f4add(a, s4[t + 256]); f4add(a, s4[t + 512]); f4add(a, s4[t + 768]);
        s4b[t] = a;
    }
    __syncthreads();
    if (t < 16) {                             // 256 -> 16, fixed order
        float4 a = s4b[t];
        #pragma unroll
        for (int m = 1; m < 16; ++m) f4add(a, s4b[t + 16 * m]);
        g_pproj4[b * 16 + t] = a;             // colgroup t
    }
    __threadfence();
    __syncthreads();

    if (t == 0) s_ticket = atomicAdd(&g_cnt, 1ULL);
    __syncthreads();
    const unsigned long long ticket = s_ticket;
    const unsigned long long launch = ticket / GRID;     // replay epoch
    const unsigned tgt = (unsigned)(launch + 1);

    if (ticket % GRID == GRID - 1) {
        __threadfence();                      // acquire: all g_pproj4 visible
        // ---- C: reduce 128x16 float4 (32 KB); 2 indep coalesced loads ----
        {
            float4 a  = __ldcg(&g_pproj4[t]);            // colgroup = t & 15
            float4 v1 = __ldcg(&g_pproj4[t + 1024]);     // same colgroup
            f4add(a, v1);
            s4[t] = a;
        }
        __syncthreads();
        if (t < 256) {
            float4 a = s4[t];
            f4add(a, s4[t + 256]); f4add(a, s4[t + 512]); f4add(a, s4[t + 768]);
            s4b[t] = a;
        }
        __syncthreads();
        if (t < 16) {                         // 256 -> 16, fixed order
            float4 a = s4b[t];
            #pragma unroll
            for (int m = 1; m < 16; ++m) f4add(a, s4b[t + 16 * m]);
            const float inv = 1.0f / (float)N_ROWSC;
            a.x = fmaxf(a.x * inv, 0.f); a.y = fmaxf(a.y * inv, 0.f);
            a.z = fmaxf(a.z * inv, 0.f); a.w = fmaxf(a.w * inv, 0.f);
            g_row4[t] = a;                    // for the 127 waiters
            srow4[t]  = a;                    // reducer's own broadcast source
        }
        __threadfence();
        __syncthreads();
        if (t == 0) g_flag = tgt;             // release (fence above)
    } else {
        // ---- Waiters: single-word spin with light backoff ----
        if (t == 0) {
            while (g_flag != tgt) __nanosleep(32);
            __threadfence();                  // acquire
        }
        __syncthreads();
        if (t < 16) srow4[t] = __ldcg(&g_row4[t]);
        __syncthreads();
    }

    // ---- D: broadcast; each block writes its 1024-float4 slice (1 store/thread) ----
    out[b * THREADS + t] = srow4[t & 15];     // 1024 % 16 == 0 -> colgroup = t & 15

    (void)OUT_F4;
}

extern "C" void kernel_launch(void* const* d_in, const int* in_sizes, int n_in,
                              void* d_out, int out_size) {
    (void)in_sizes; (void)n_in; (void)out_size;
    const float* h = (const float*)d_in[0];   // (8192, 512) fp32
    // d_in[1] = adj (8192,8192) -- dead code, never read
    const float* W = (const float*)d_in[2];   // (512, 64) fp32
    // d_in[3] = a (128,1)       -- dead code, never read
    float* out = (float*)d_out;               // (8192, 64) fp32

    gat_kernel<<<GRID, THREADS>>>((const float4*)h, (const float4*)W,
                                  (float4*)out);
}

// round 13
// speedup vs baseline: 1.4295x; 1.2100x over previous
#include <cuda_runtime.h>

// Reference collapses: softmax(const(-9e15)) == uniform 1/N  =>  adj/a/e dead.
//   out[i,:] = relu( (colsum(h) @ W) / N )  -- one 64-float row broadcast 8192x.
// TWO kernels, NO interlock (graph edge is the sync; no atomics/spins/fences):
//   K1: partial column sums + per-block projection -> g_pproj4 (32 KB)
//   K2: every block redundantly reduces the 32 KB payload (L2 broadcast),
//       normalizes + relu, writes its own 4 KB output slice.

#define N_ROWSC 8192
#define F_INC   512
#define F_OUTC  64
#define GRID    128
#define THREADS 1024
#define TOTAL_F4 (N_ROWSC * F_INC / 4)        // 1,048,576
#define STRIDE   (GRID * THREADS)             // 131,072 (multiple of 128)
#define LOADS_PT (TOTAL_F4 / STRIDE)          // 8 (exact)
#define OUT_F4   (N_ROWSC * F_OUTC / 4)       // 131,072 (1024 per block)

__device__ float4 g_pproj4[GRID * 16];        // 32 KB per-block projections

__device__ __forceinline__ void f4add(float4& a, const float4& v) {
    a.x += v.x; a.y += v.y; a.z += v.z; a.w += v.w;
}

// ---- K1: colsum partials + per-block projection (R12 phases A+B, proven) ----
__global__ __launch_bounds__(THREADS)
void k1_colsum_project(const float4* __restrict__ h4,
                       const float4* __restrict__ W4)
{
    __shared__ float4 s4[THREADS];            // 16 KB
    __shared__ float4 s4b[256];               // 4 KB
    __shared__ float  sf[F_INC];              // 2 KB

    const int t = threadIdx.x;
    const int b = blockIdx.x;

    // A: partial column sums; 8 independent float4 loads, exact cover.
    {
        const int gid = b * THREADS + t;      // stride mult of 128 -> colgrp = t & 127
        float4 acc = make_float4(0.f, 0.f, 0.f, 0.f);
        #pragma unroll
        for (int k = 0; k < LOADS_PT; ++k) {
            float4 v = h4[gid + k * STRIDE];
            f4add(acc, v);                    // fixed order -> deterministic
        }
        s4[t] = acc;
    }
    __syncthreads();
    if (t < 128) {                            // 8 partials per column group, fixed order
        float4 a = s4[t];
        #pragma unroll
        for (int j = 1; j < 8; ++j) f4add(a, s4[t + 128 * j]);
        sf[t * 4 + 0] = a.x; sf[t * 4 + 1] = a.y;
        sf[t * 4 + 2] = a.z; sf[t * 4 + 3] = a.w;
    }
    __syncthreads();

    // B: project colsum through W; i = t + j*1024 covers W exactly once.
    // colgroup(i) = i & 15 = t & 15 (constant per thread); k(i) = i >> 4.
    {
        float4 po = make_float4(0.f, 0.f, 0.f, 0.f);
        #pragma unroll
        for (int j = 0; j < 8; ++j) {
            const float4 w = W4[t + j * THREADS];   // L2-served after first blocks
            const float  s = sf[(t >> 4) + j * 64];
            po.x = fmaf(s, w.x, po.x); po.y = fmaf(s, w.y, po.y);
            po.z = fmaf(s, w.z, po.z); po.w = fmaf(s, w.w, po.w);
        }
        s4[t] = po;
    }
    __syncthreads();
    if (t < 256) {                            // 1024 -> 256, same colgroup (t&15)
        float4 a = s4[t];
        f4add(a, s4[t + 256]); f4add(a, s4[t + 512]); f4add(a, s4[t + 768]);
        s4b[t] = a;
    }
    __syncthreads();
    if (t < 16) {                             // 256 -> 16, fixed order
        float4 a = s4b[t];
        #pragma unroll
        for (int m = 1; m < 16; ++m) f4add(a, s4b[t + 16 * m]);
        g_pproj4[b * 16 + t] = a;             // colgroup t
    }
}

// ---- K2: redundant per-block reduce of 32 KB payload + broadcast slice ----
__global__ __launch_bounds__(THREADS)
void k2_reduce_broadcast(float4* __restrict__ out)
{
    __shared__ float4 s4[THREADS];            // 16 KB
    __shared__ float4 s4b[256];               // 4 KB
    __shared__ float4 srow4[16];              // 256 B

    const int t = threadIdx.x;
    const int b = blockIdx.x;

    // 2 independent coalesced loads/thread over the 2048-float4 payload (L2).
    {
        float4 a  = __ldcg(&g_pproj4[t]);            // colgroup = t & 15
        float4 v1 = __ldcg(&g_pproj4[t + 1024]);     // same colgroup
        f4add(a, v1);
        s4[t] = a;
    }
    __syncthreads();
    if (t < 256) {                            // 1024 -> 256, same colgroup
        float4 a = s4[t];
        f4add(a, s4[t + 256]); f4add(a, s4[t + 512]); f4add(a, s4[t + 768]);
        s4b[t] = a;
    }
    __syncthreads();
    if (t < 16) {                             // 256 -> 16, fixed order
        float4 a = s4b[t];
        #pragma unroll
        for (int m = 1; m < 16; ++m) f4add(a, s4b[t + 16 * m]);
        const float inv = 1.0f / (float)N_ROWSC;
        a.x = fmaxf(a.x * inv, 0.f); a.y = fmaxf(a.y * inv, 0.f);
        a.z = fmaxf(a.z * inv, 0.f); a.w = fmaxf(a.w * inv, 0.f);
        srow4[t] = a;
    }
    __syncthreads();

    // Broadcast: each block writes its 1024-float4 slice (1 store/thread).
    out[b * THREADS + t] = srow4[t & 15];     // 1024 % 16 == 0 -> colgroup = t & 15

    (void)OUT_F4;
}

extern "C" void kernel_launch(void* const* d_in, const int* in_sizes, int n_in,
                              void* d_out, int out_size) {
    (void)in_sizes; (void)n_in; (void)out_size;
    const float* h = (const float*)d_in[0];   // (8192, 512) fp32
    // d_in[1] = adj (8192,8192) -- dead code, never read
    const float* W = (const float*)d_in[2];   // (512, 64) fp32
    // d_in[3] = a (128,1)       -- dead code, never read
    float* out = (float*)d_out;               // (8192, 64) fp32

    k1_colsum_project<<<GRID, THREADS>>>((const float4*)h, (const float4*)W);
    k2_reduce_broadcast<<<GRID, THREADS>>>((float4*)out);
}